// round 6
// baseline (speedup 1.0000x reference)
#include <cuda_runtime.h>
#include <math.h>

#define BB 32
#define TT 512
#define II 1024
#define HH 1024
#define GG 4096   // 4*H

// ---- scratch (static __device__ arrays; no allocation allowed) ----
__device__ float g_xproj[67108864];            // [T][B][4H] = 512*32*4096 (256 MB)
__device__ float g_part[16 * 8 * 32 * 512];    // [ks16][tile8][m32][n512] partials (8 MB)
__device__ float g_h[2][BB * HH];              // ping-pong hidden state
__device__ float g_c[BB * HH];                 // cell state
__device__ unsigned g_bar_cnt;
__device__ volatile unsigned g_bar_gen;

__device__ __forceinline__ float sigmoidf_(float x) {
    return 1.0f / (1.0f + __expf(-x));
}

// packed f32x2 FMA: d(lo,hi) += a(lo,hi) * b(lo,hi)
__device__ __forceinline__ void ffma2(unsigned long long& d,
                                      unsigned long long a,
                                      unsigned long long b) {
    asm("fma.rn.f32x2 %0, %1, %2, %0;" : "+l"(d) : "l"(a), "l"(b));
}

__device__ __forceinline__ float2 u2f2(unsigned long long v) {
    float2 f;
    f.x = __uint_as_float((unsigned)v);
    f.y = __uint_as_float((unsigned)(v >> 32));
    return f;
}

__device__ __forceinline__ unsigned long long dupf(float v) {
    unsigned u = __float_as_uint(v);
    return ((unsigned long long)u << 32) | u;
}

// ---------------------------------------------------------------------------
// init: h <- h0, c <- c0, barrier reset  (re-run every replay for determinism)
// ---------------------------------------------------------------------------
__global__ void init_kernel(const float* __restrict__ h0, const float* __restrict__ c0) {
    int i = blockIdx.x * blockDim.x + threadIdx.x;
    if (i < BB * HH) { g_h[0][i] = h0[i]; g_c[i] = c0[i]; }
    if (i == 0) { g_bar_cnt = 0; g_bar_gen = 0; }
}

// ---------------------------------------------------------------------------
// x_proj = x @ Wi^T + bi + bh   (row r = t*32 + b <-> x[b][t][:])
// M=16384, N=4096, K=1024.  BM=BN=128, BK=16, 256 thr, 8x8 microtile,
// math via packed fma.rn.f32x2 (A duplicated into (a,a) u64 pairs in SMEM,
// B pairs taken from adjacent N columns).
// ---------------------------------------------------------------------------
__global__ __launch_bounds__(256, 2) void xproj_kernel(
    const float* __restrict__ x, const float* __restrict__ Wi,
    const float* __restrict__ bi, const float* __restrict__ bh)
{
    __shared__ __align__(16) unsigned long long As[16][128]; // dup pairs [k][m]
    __shared__ __align__(16) float Bs[16][132];              // [k][n]
    const int bn  = blockIdx.x;   // 0..31
    const int bm  = blockIdx.y;   // 0..127
    const int tid = threadIdx.x;
    const int tx  = tid & 15, ty = tid >> 4;

    unsigned long long acc[8][4];
#pragma unroll
    for (int i = 0; i < 8; i++)
#pragma unroll
        for (int j = 0; j < 4; j++) acc[i][j] = 0ULL;

    for (int k0 = 0; k0 < II; k0 += 16) {
#pragma unroll
        for (int u = 0; u < 2; u++) {
            int id  = tid + u * 256;
            int row = id >> 2;
            int k4  = (id & 3) << 2;
            int grow = bm * 128 + row;
            const float4 va = *(const float4*)(
                x + ((size_t)(grow & 31) * TT + (grow >> 5)) * II + k0 + k4);
            As[k4 + 0][row] = dupf(va.x);
            As[k4 + 1][row] = dupf(va.y);
            As[k4 + 2][row] = dupf(va.z);
            As[k4 + 3][row] = dupf(va.w);
            const float4 vb = *(const float4*)(
                Wi + (size_t)(bn * 128 + row) * II + k0 + k4);
            Bs[k4 + 0][row] = vb.x; Bs[k4 + 1][row] = vb.y;
            Bs[k4 + 2][row] = vb.z; Bs[k4 + 3][row] = vb.w;
        }
        __syncthreads();
#pragma unroll
        for (int k = 0; k < 16; k++) {
            const unsigned long long* ar = &As[k][ty * 8];
            ulonglong2 A0 = *(const ulonglong2*)(ar + 0);
            ulonglong2 A1 = *(const ulonglong2*)(ar + 2);
            ulonglong2 A2 = *(const ulonglong2*)(ar + 4);
            ulonglong2 A3 = *(const ulonglong2*)(ar + 6);
            const float* br = &Bs[k][tx * 8];
            ulonglong2 B0 = *(const ulonglong2*)(br + 0);  // (n0,n1),(n2,n3)
            ulonglong2 B1 = *(const ulonglong2*)(br + 4);  // (n4,n5),(n6,n7)
            unsigned long long av[8] = {A0.x, A0.y, A1.x, A1.y, A2.x, A2.y, A3.x, A3.y};
            unsigned long long bv[4] = {B0.x, B0.y, B1.x, B1.y};
#pragma unroll
            for (int i = 0; i < 8; i++)
#pragma unroll
                for (int j = 0; j < 4; j++)
                    ffma2(acc[i][j], av[i], bv[j]);
        }
        __syncthreads();
    }

    const int colbase = bn * 128 + tx * 8;
    float bias[8];
#pragma unroll
    for (int j = 0; j < 8; j++) bias[j] = bi[colbase + j] + bh[colbase + j];
#pragma unroll
    for (int i = 0; i < 8; i++) {
        int row = bm * 128 + ty * 8 + i;
        float* dst = g_xproj + (size_t)row * GG + colbase;
        float2 c0 = u2f2(acc[i][0]), c1 = u2f2(acc[i][1]);
        float2 c2 = u2f2(acc[i][2]), c3 = u2f2(acc[i][3]);
        *(float4*)(dst)     = make_float4(c0.x + bias[0], c0.y + bias[1],
                                          c1.x + bias[2], c1.y + bias[3]);
        *(float4*)(dst + 4) = make_float4(c2.x + bias[4], c2.y + bias[5],
                                          c3.x + bias[6], c3.y + bias[7]);
    }
}

// ---------------------------------------------------------------------------
// Persistent recurrence kernel (unchanged from R5 — at its f32x2 roofline).
// 128 blocks x 256 thr, all co-resident. Block = (tile = bx>>4, ks = bx&15).
// tile owns hcols [tile*128, +128) across all 4 gates -> 512 gate cols.
// ks owns K slice [ks*64, +64). Wh slice (64k x 512n = 128KB) lives in SMEM
// for the whole kernel. Two grid barriers per step; reduction+activation is
// spread over all 128 blocks (8 hcols x 32 b each), fixed order = deterministic.
// ---------------------------------------------------------------------------
__device__ __forceinline__ void grid_sync(unsigned& gen) {
    __syncthreads();
    if (threadIdx.x == 0) {
        __threadfence();
        unsigned arrived = atomicAdd(&g_bar_cnt, 1u);
        if (arrived == gridDim.x - 1) {
            g_bar_cnt = 0;
            __threadfence();
            g_bar_gen = gen + 1;
        } else {
            while (g_bar_gen <= gen) { }
            __threadfence();
        }
    }
    gen++;
    __syncthreads();
}

__global__ __launch_bounds__(256, 1) void lstm_persist(
    const float* __restrict__ Wh, float* __restrict__ out)
{
    extern __shared__ char smem_raw[];
    float* Wh_s = (float*)smem_raw;                                        // [64][512]
    unsigned long long* h_dup = (unsigned long long*)(smem_raw + 131072);  // [64][32]

    const int bx   = blockIdx.x;
    const int tile = bx >> 4;     // 0..7
    const int ks   = bx & 15;     // 0..15
    const int tid  = threadIdx.x;
    const int tx   = tid & 63;    // n-group
    const int ty   = tid >> 6;    // m-group (0..3)
    const int kbase = ks * 64;

    // ---- one-time: load Wh slice into SMEM (transposed to [k][n]) ----
#pragma unroll 4
    for (int u = 0; u < 32; u++) {
        int idx = tid + u * 256;       // 0..8191 = (n, kq)
        int n   = idx >> 4;            // 0..511
        int kq  = idx & 15;            // 0..15 (float4 along k)
        int g   = n >> 7;
        int hc  = tile * 128 + (n & 127);
        const float4 v = *(const float4*)(Wh + (size_t)(g * HH + hc) * HH + kbase + kq * 4);
        Wh_s[(kq * 4 + 0) * 512 + n] = v.x;
        Wh_s[(kq * 4 + 1) * 512 + n] = v.y;
        Wh_s[(kq * 4 + 2) * 512 + n] = v.z;
        Wh_s[(kq * 4 + 3) * 512 + n] = v.w;
    }

    const int rb = tid >> 3;   // batch (0..31): h-load + reduction role
    const int rh = tid & 7;    // hcol-local / k-group

    unsigned gen = 0;

    for (int t = 0; t < TT; t++) {
        const float* h_in  = g_h[t & 1];
        float*       h_out = g_h[(t + 1) & 1];

        // ---- load h slice into SMEM, duplicated into f32x2 pairs ----
        {
            int koff = rh * 8;
            const float4 v0 = *(const float4*)(h_in + rb * HH + kbase + koff);
            const float4 v1 = *(const float4*)(h_in + rb * HH + kbase + koff + 4);
            float vv[8] = {v0.x, v0.y, v0.z, v0.w, v1.x, v1.y, v1.z, v1.w};
#pragma unroll
            for (int i = 0; i < 8; i++)
                h_dup[(koff + i) * 32 + rb] = dupf(vv[i]);
        }
        __syncthreads();

        // ---- GEMM: acc[8m][8n] via packed f32x2 FMA ----
        unsigned long long acc[8][4];
#pragma unroll
        for (int i = 0; i < 8; i++)
#pragma unroll
            for (int j = 0; j < 4; j++) acc[i][j] = 0ULL;

#pragma unroll 4
        for (int k = 0; k < 64; k++) {
            const unsigned long long* hr = h_dup + (k << 5) + (ty << 3);
            ulonglong2 A0 = *(const ulonglong2*)(hr + 0);
            ulonglong2 A1 = *(const ulonglong2*)(hr + 2);
            ulonglong2 A2 = *(const ulonglong2*)(hr + 4);
            ulonglong2 A3 = *(const ulonglong2*)(hr + 6);
            const float* wr = Wh_s + (k << 9);
            ulonglong2 B0 = *(const ulonglong2*)(wr + (tx << 2));
            ulonglong2 B1 = *(const ulonglong2*)(wr + 256 + (tx << 2));
            unsigned long long av[8] = {A0.x, A0.y, A1.x, A1.y, A2.x, A2.y, A3.x, A3.y};
            unsigned long long bv[4] = {B0.x, B0.y, B1.x, B1.y};
#pragma unroll
            for (int i = 0; i < 8; i++)
#pragma unroll
                for (int j = 0; j < 4; j++)
                    ffma2(acc[i][j], av[i], bv[j]);
        }

        // ---- publish partials: g_part[ks][tile][m][n] ----
        float* pb = g_part + ((size_t)(ks * 8 + tile) * 32) * 512;
#pragma unroll
        for (int i = 0; i < 8; i++) {
            int m = ty * 8 + i;
            float2 c0 = u2f2(acc[i][0]), c1 = u2f2(acc[i][1]);
            float2 c2 = u2f2(acc[i][2]), c3 = u2f2(acc[i][3]);
            *(float4*)(pb + m * 512 + tx * 4)       = make_float4(c0.x, c0.y, c1.x, c1.y);
            *(float4*)(pb + m * 512 + 256 + tx * 4) = make_float4(c2.x, c2.y, c3.x, c3.y);
        }

        grid_sync(gen);

        // ---- parallel reduction + activations (1 (b, hc) item per thread) ----
        {
            int hc    = bx * 8 + rh;          // 0..1023
            int rtile = hc >> 7;
            int nb    = hc & 127;
            float s0 = 0.f, s1 = 0.f, s2 = 0.f, s3 = 0.f;
            const float* gp = g_part + ((size_t)rtile * 32 + rb) * 512 + nb;
#pragma unroll
            for (int kk = 0; kk < 16; kk++) {
                const float* p = gp + (size_t)kk * 8 * 32 * 512;
                s0 += p[0]; s1 += p[128]; s2 += p[256]; s3 += p[384];
            }
            const float* xp = g_xproj + ((size_t)t * BB + rb) * GG + hc;
            s0 += xp[0]; s1 += xp[HH]; s2 += xp[2 * HH]; s3 += xp[3 * HH];

            float ig = sigmoidf_(s0);
            float fg = sigmoidf_(s1);
            float gg = tanhf(s2);
            float og = sigmoidf_(s3);
            float c_old = g_c[rb * HH + hc];
            float c_new = fmaf(fg, c_old, ig * gg);
            float h_new = og * tanhf(c_new);
            g_c[rb * HH + hc]   = c_new;
            h_out[rb * HH + hc] = h_new;
            out[(size_t)rb * TT * HH + (size_t)t * HH + hc] = h_new;
        }

        grid_sync(gen);
    }
}

// ---------------------------------------------------------------------------
// tail: h_T, c_T appended after output [B,T,H]
// ---------------------------------------------------------------------------
__global__ void finish_kernel(float* __restrict__ out) {
    int i = blockIdx.x * blockDim.x + threadIdx.x;
    if (i < BB * HH) {
        out[(size_t)BB * TT * HH + i]           = g_h[0][i];   // 512 steps -> buf 0
        out[(size_t)BB * TT * HH + BB * HH + i] = g_c[i];
    }
}

extern "C" void kernel_launch(void* const* d_in, const int* in_sizes, int n_in,
                              void* d_out, int out_size) {
    const float* x  = (const float*)d_in[0];
    const float* h0 = (const float*)d_in[1];
    const float* c0 = (const float*)d_in[2];
    const float* Wi = (const float*)d_in[3];
    const float* bi = (const float*)d_in[4];
    const float* Wh = (const float*)d_in[5];
    const float* bh = (const float*)d_in[6];
    float* out = (float*)d_out;

    cudaFuncSetAttribute(lstm_persist, cudaFuncAttributeMaxDynamicSharedMemorySize,
                         131072 + 16384);

    init_kernel<<<(BB * HH + 255) / 256, 256>>>(h0, c0);
    xproj_kernel<<<dim3(32, 128), 256>>>(x, Wi, bi, bh);
    lstm_persist<<<128, 256, 131072 + 16384>>>(Wh, out);
    finish_kernel<<<(BB * HH + 255) / 256, 256>>>(out);
}

// round 8
// speedup vs baseline: 1.3184x; 1.3184x over previous
#include <cuda_runtime.h>
#include <cuda_bf16.h>
#include <math.h>
#include <stdint.h>

#define BB 32
#define TT 512
#define II 1024
#define HH 1024
#define GG 4096   // 4*H

// ---- scratch (static __device__ arrays; no allocation allowed) ----
__device__ float g_xproj[67108864];            // [T][B][4H] (256 MB)
__device__ float g_part[16 * 8 * 32 * 512];    // recurrence partials (8 MB)
__device__ float g_h[2][BB * HH];
__device__ float g_c[BB * HH];
__device__ unsigned g_bar_cnt;
__device__ volatile unsigned g_bar_gen;
// bf16 hi/lo split operands for tensor-core xproj
__device__ __nv_bfloat16 g_xhi[TT * BB * II];  // [r=t*32+b][i]
__device__ __nv_bfloat16 g_xlo[TT * BB * II];
__device__ __nv_bfloat16 g_whi[GG * II];       // [n][k]
__device__ __nv_bfloat16 g_wlo[GG * II];

__device__ __forceinline__ float sigmoidf_(float x) {
    return 1.0f / (1.0f + __expf(-x));
}

// packed f32x2 FMA (recurrence kernel)
__device__ __forceinline__ void ffma2(unsigned long long& d,
                                      unsigned long long a,
                                      unsigned long long b) {
    asm("fma.rn.f32x2 %0, %1, %2, %0;" : "+l"(d) : "l"(a), "l"(b));
}
__device__ __forceinline__ float2 u2f2(unsigned long long v) {
    float2 f;
    f.x = __uint_as_float((unsigned)v);
    f.y = __uint_as_float((unsigned)(v >> 32));
    return f;
}
__device__ __forceinline__ unsigned long long dupf(float v) {
    unsigned u = __float_as_uint(v);
    return ((unsigned long long)u << 32) | u;
}

__device__ __forceinline__ uint32_t smem_u32(const void* p) {
    uint32_t a;
    asm("{ .reg .u64 t; cvta.to.shared.u64 t, %1; cvt.u32.u64 %0, t; }"
        : "=r"(a) : "l"(p));
    return a;
}

// ldmatrix x4 (sm_75+)
__device__ __forceinline__ void ldsm4(uint32_t* r, uint32_t addr) {
    asm volatile("ldmatrix.sync.aligned.m8n8.x4.shared.b16 {%0,%1,%2,%3}, [%4];"
                 : "=r"(r[0]), "=r"(r[1]), "=r"(r[2]), "=r"(r[3]) : "r"(addr));
}
// mma.sync bf16 (sm_80+)
__device__ __forceinline__ void mma16816(float* c, const uint32_t* a,
                                         uint32_t b0, uint32_t b1) {
    asm volatile(
        "mma.sync.aligned.m16n8k16.row.col.f32.bf16.bf16.f32 "
        "{%0,%1,%2,%3}, {%4,%5,%6,%7}, {%8,%9}, {%0,%1,%2,%3};"
        : "+f"(c[0]), "+f"(c[1]), "+f"(c[2]), "+f"(c[3])
        : "r"(a[0]), "r"(a[1]), "r"(a[2]), "r"(a[3]), "r"(b0), "r"(b1));
}

// ---------------------------------------------------------------------------
// init + bf16 split conversions
// ---------------------------------------------------------------------------
__global__ void init_kernel(const float* __restrict__ h0, const float* __restrict__ c0) {
    int i = blockIdx.x * blockDim.x + threadIdx.x;
    if (i < BB * HH) { g_h[0][i] = h0[i]; g_c[i] = c0[i]; }
    if (i == 0) { g_bar_cnt = 0; g_bar_gen = 0; }
}

__device__ __forceinline__ void split4(float4 v, __nv_bfloat16* hi, __nv_bfloat16* lo,
                                       size_t r) {
    float vv[4] = {v.x, v.y, v.z, v.w};
    __nv_bfloat16 h[4], l[4];
#pragma unroll
    for (int j = 0; j < 4; j++) {
        h[j] = __float2bfloat16(vv[j]);
        l[j] = __float2bfloat16(vv[j] - __bfloat162float(h[j]));
    }
    *(__nv_bfloat162*)(hi + r)     = __halves2bfloat162(h[0], h[1]);
    *(__nv_bfloat162*)(hi + r + 2) = __halves2bfloat162(h[2], h[3]);
    *(__nv_bfloat162*)(lo + r)     = __halves2bfloat162(l[0], l[1]);
    *(__nv_bfloat162*)(lo + r + 2) = __halves2bfloat162(l[2], l[3]);
}

__global__ void conv_x_kernel(const float* __restrict__ x) {
    int64_t n4 = (int64_t)TT * BB * II / 4;
    for (int64_t q = blockIdx.x * blockDim.x + threadIdx.x; q < n4;
         q += (int64_t)gridDim.x * blockDim.x) {
        int64_t i4 = q * 4;
        int i  = (int)(i4 & (II - 1));
        int bt = (int)(i4 >> 10);
        int t  = bt & (TT - 1);
        int b  = bt >> 9;
        float4 v = *(const float4*)(x + i4);
        size_t r = ((size_t)t * BB + b) * II + i;
        split4(v, g_xhi, g_xlo, r);
    }
}

__global__ void conv_w_kernel(const float* __restrict__ Wi) {
    int64_t n4 = (int64_t)GG * II / 4;
    for (int64_t q = blockIdx.x * blockDim.x + threadIdx.x; q < n4;
         q += (int64_t)gridDim.x * blockDim.x) {
        float4 v = *(const float4*)(Wi + q * 4);
        split4(v, g_whi, g_wlo, (size_t)q * 4);
    }
}

// ---------------------------------------------------------------------------
// xproj GEMM via mma.sync bf16 (hi/lo split, 3 passes, fp32 accumulate).
// D[16384, 4096] = Xsplit @ Wsplit^T + (bi + bh).
// CTA 128m x 128n, BK=64, 256 thr (8 warps: 4m x 2n, warp tile 32x64).
// ---------------------------------------------------------------------------
#define LDP 72    // padded row stride in bf16 (144 B, conflict-free ldmatrix)
#define XP_SMEM (4 * 128 * LDP * 2)

__global__ __launch_bounds__(256, 2) void xproj_mma_kernel(
    const float* __restrict__ bi, const float* __restrict__ bh,
    float* __restrict__ outbuf)
{
    extern __shared__ char smem[];
    __nv_bfloat16* Ah = (__nv_bfloat16*)smem;        // [128][LDP]
    __nv_bfloat16* Al = Ah + 128 * LDP;
    __nv_bfloat16* Bh = Al + 128 * LDP;
    __nv_bfloat16* Bl = Bh + 128 * LDP;

    const int tid  = threadIdx.x;
    const int w    = tid >> 5;
    const int lane = tid & 31;
    const int ntile = blockIdx.x;   // 0..31
    const int mtile = blockIdx.y;   // 0..127
    const int wm = (w >> 1) * 32;   // warp m offset in tile
    const int wn = (w & 1) * 64;    // warp n offset in tile

    const __nv_bfloat16* gAh = g_xhi + (size_t)(mtile * 128) * II;
    const __nv_bfloat16* gAl = g_xlo + (size_t)(mtile * 128) * II;
    const __nv_bfloat16* gBh = g_whi + (size_t)(ntile * 128) * II;
    const __nv_bfloat16* gBl = g_wlo + (size_t)(ntile * 128) * II;

    float acc[2][8][4];
#pragma unroll
    for (int mi = 0; mi < 2; mi++)
#pragma unroll
        for (int nj = 0; nj < 8; nj++)
#pragma unroll
            for (int q = 0; q < 4; q++) acc[mi][nj][q] = 0.f;

    // precomputed ldmatrix lane address components
    const int a_row = lane & 15;
    const int a_col = (lane >> 4) << 3;              // 0 or 8 (k-half)
    const int b_row = ((lane >> 4) << 3) + (lane & 7);
    const int b_col = ((lane >> 3) & 1) << 3;        // 0 or 8 (k-half)

    for (int chunk = 0; chunk < 16; chunk++) {
        const int k0 = chunk * 64;
#pragma unroll
        for (int it = 0; it < 4; it++) {
            int idx = tid + it * 256;      // 0..1023
            int row = idx >> 3;
            int cg  = idx & 7;
            size_t g = (size_t)row * II + k0 + cg * 8;
            int s = row * LDP + cg * 8;
            *(uint4*)(Ah + s) = *(const uint4*)(gAh + g);
            *(uint4*)(Al + s) = *(const uint4*)(gAl + g);
            *(uint4*)(Bh + s) = *(const uint4*)(gBh + g);
            *(uint4*)(Bl + s) = *(const uint4*)(gBl + g);
        }
        __syncthreads();

#pragma unroll
        for (int kk = 0; kk < 4; kk++) {
            const int ks = kk * 16;
            uint32_t ah[2][4], al[2][4];
#pragma unroll
            for (int mi = 0; mi < 2; mi++) {
                ldsm4(ah[mi], smem_u32(Ah + (wm + mi * 16 + a_row) * LDP + ks + a_col));
                ldsm4(al[mi], smem_u32(Al + (wm + mi * 16 + a_row) * LDP + ks + a_col));
            }
#pragma unroll
            for (int g2 = 0; g2 < 4; g2++) {
                uint32_t bh4[4], bl4[4];
                ldsm4(bh4, smem_u32(Bh + (wn + g2 * 16 + b_row) * LDP + ks + b_col));
                ldsm4(bl4, smem_u32(Bl + (wn + g2 * 16 + b_row) * LDP + ks + b_col));
#pragma unroll
                for (int mi = 0; mi < 2; mi++) {
                    mma16816(acc[mi][g2 * 2],     ah[mi], bh4[0], bh4[1]);
                    mma16816(acc[mi][g2 * 2],     ah[mi], bl4[0], bl4[1]);
                    mma16816(acc[mi][g2 * 2],     al[mi], bh4[0], bh4[1]);
                    mma16816(acc[mi][g2 * 2 + 1], ah[mi], bh4[2], bh4[3]);
                    mma16816(acc[mi][g2 * 2 + 1], ah[mi], bl4[2], bl4[3]);
                    mma16816(acc[mi][g2 * 2 + 1], al[mi], bh4[2], bh4[3]);
                }
            }
        }
        __syncthreads();
    }

    // epilogue: c0,c1 -> (row, col..col+1); c2,c3 -> (row+8, col..col+1)
    const int colw = ntile * 128 + wn;
#pragma unroll
    for (int mi = 0; mi < 2; mi++) {
        int r0 = mtile * 128 + wm + mi * 16 + (lane >> 2);
#pragma unroll
        for (int nj = 0; nj < 8; nj++) {
            int c = colw + nj * 8 + (lane & 3) * 2;
            float b0 = bi[c] + bh[c];
            float b1 = bi[c + 1] + bh[c + 1];
            *(float2*)(outbuf + (size_t)r0 * GG + c) =
                make_float2(acc[mi][nj][0] + b0, acc[mi][nj][1] + b1);
            *(float2*)(outbuf + (size_t)(r0 + 8) * GG + c) =
                make_float2(acc[mi][nj][2] + b0, acc[mi][nj][3] + b1);
        }
    }
}

// ---------------------------------------------------------------------------
// Persistent recurrence kernel (unchanged — validated R5 version).
// ---------------------------------------------------------------------------
__device__ __forceinline__ void grid_sync(unsigned& gen) {
    __syncthreads();
    if (threadIdx.x == 0) {
        __threadfence();
        unsigned arrived = atomicAdd(&g_bar_cnt, 1u);
        if (arrived == gridDim.x - 1) {
            g_bar_cnt = 0;
            __threadfence();
            g_bar_gen = gen + 1;
        } else {
            while (g_bar_gen <= gen) { }
            __threadfence();
        }
    }
    gen++;
    __syncthreads();
}

__global__ __launch_bounds__(256, 1) void lstm_persist(
    const float* __restrict__ Wh, float* __restrict__ out)
{
    extern __shared__ char smem_raw[];
    float* Wh_s = (float*)smem_raw;                                        // [64][512]
    unsigned long long* h_dup = (unsigned long long*)(smem_raw + 131072);  // [64][32]

    const int bx   = blockIdx.x;
    const int tile = bx >> 4;
    const int ks   = bx & 15;
    const int tid  = threadIdx.x;
    const int tx   = tid & 63;
    const int ty   = tid >> 6;
    const int kbase = ks * 64;

#pragma unroll 4
    for (int u = 0; u < 32; u++) {
        int idx = tid + u * 256;
        int n   = idx >> 4;
        int kq  = idx & 15;
        int g   = n >> 7;
        int hc  = tile * 128 + (n & 127);
        const float4 v = *(const float4*)(Wh + (size_t)(g * HH + hc) * HH + kbase + kq * 4);
        Wh_s[(kq * 4 + 0) * 512 + n] = v.x;
        Wh_s[(kq * 4 + 1) * 512 + n] = v.y;
        Wh_s[(kq * 4 + 2) * 512 + n] = v.z;
        Wh_s[(kq * 4 + 3) * 512 + n] = v.w;
    }

    const int rb = tid >> 3;
    const int rh = tid & 7;

    unsigned gen = 0;

    for (int t = 0; t < TT; t++) {
        const float* h_in  = g_h[t & 1];
        float*       h_out = g_h[(t + 1) & 1];

        {
            int koff = rh * 8;
            const float4 v0 = *(const float4*)(h_in + rb * HH + kbase + koff);
            const float4 v1 = *(const float4*)(h_in + rb * HH + kbase + koff + 4);
            float vv[8] = {v0.x, v0.y, v0.z, v0.w, v1.x, v1.y, v1.z, v1.w};
#pragma unroll
            for (int i = 0; i < 8; i++)
                h_dup[(koff + i) * 32 + rb] = dupf(vv[i]);
        }
        __syncthreads();

        unsigned long long acc[8][4];
#pragma unroll
        for (int i = 0; i < 8; i++)
#pragma unroll
            for (int j = 0; j < 4; j++) acc[i][j] = 0ULL;

#pragma unroll 4
        for (int k = 0; k < 64; k++) {
            const unsigned long long* hr = h_dup + (k << 5) + (ty << 3);
            ulonglong2 A0 = *(const ulonglong2*)(hr + 0);
            ulonglong2 A1 = *(const ulonglong2*)(hr + 2);
            ulonglong2 A2 = *(const ulonglong2*)(hr + 4);
            ulonglong2 A3 = *(const ulonglong2*)(hr + 6);
            const float* wr = Wh_s + (k << 9);
            ulonglong2 B0 = *(const ulonglong2*)(wr + (tx << 2));
            ulonglong2 B1 = *(const ulonglong2*)(wr + 256 + (tx << 2));
            unsigned long long av[8] = {A0.x, A0.y, A1.x, A1.y, A2.x, A2.y, A3.x, A3.y};
            unsigned long long bv[4] = {B0.x, B0.y, B1.x, B1.y};
#pragma unroll
            for (int i = 0; i < 8; i++)
#pragma unroll
                for (int j = 0; j < 4; j++)
                    ffma2(acc[i][j], av[i], bv[j]);
        }

        float* pb = g_part + ((size_t)(ks * 8 + tile) * 32) * 512;
#pragma unroll
        for (int i = 0; i < 8; i++) {
            int m = ty * 8 + i;
            float2 c0 = u2f2(acc[i][0]), c1 = u2f2(acc[i][1]);
            float2 c2 = u2f2(acc[i][2]), c3 = u2f2(acc[i][3]);
            *(float4*)(pb + m * 512 + tx * 4)       = make_float4(c0.x, c0.y, c1.x, c1.y);
            *(float4*)(pb + m * 512 + 256 + tx * 4) = make_float4(c2.x, c2.y, c3.x, c3.y);
        }

        grid_sync(gen);

        {
            int hc    = bx * 8 + rh;
            int rtile = hc >> 7;
            int nb    = hc & 127;
            float s0 = 0.f, s1 = 0.f, s2 = 0.f, s3 = 0.f;
            const float* gp = g_part + ((size_t)rtile * 32 + rb) * 512 + nb;
#pragma unroll
            for (int kk = 0; kk < 16; kk++) {
                const float* p = gp + (size_t)kk * 8 * 32 * 512;
                s0 += p[0]; s1 += p[128]; s2 += p[256]; s3 += p[384];
            }
            const float* xp = g_xproj + ((size_t)t * BB + rb) * GG + hc;
            s0 += xp[0]; s1 += xp[HH]; s2 += xp[2 * HH]; s3 += xp[3 * HH];

            float ig = sigmoidf_(s0);
            float fg = sigmoidf_(s1);
            float gg = tanhf(s2);
            float og = sigmoidf_(s3);
            float c_old = g_c[rb * HH + hc];
            float c_new = fmaf(fg, c_old, ig * gg);
            float h_new = og * tanhf(c_new);
            g_c[rb * HH + hc]   = c_new;
            h_out[rb * HH + hc] = h_new;
            out[(size_t)rb * TT * HH + (size_t)t * HH + hc] = h_new;
        }

        grid_sync(gen);
    }
}

// ---------------------------------------------------------------------------
// tail: h_T, c_T appended after output [B,T,H]
// ---------------------------------------------------------------------------
__global__ void finish_kernel(float* __restrict__ out) {
    int i = blockIdx.x * blockDim.x + threadIdx.x;
    if (i < BB * HH) {
        out[(size_t)BB * TT * HH + i]           = g_h[0][i];
        out[(size_t)BB * TT * HH + BB * HH + i] = g_c[i];
    }
}

extern "C" void kernel_launch(void* const* d_in, const int* in_sizes, int n_in,
                              void* d_out, int out_size) {
    const float* x  = (const float*)d_in[0];
    const float* h0 = (const float*)d_in[1];
    const float* c0 = (const float*)d_in[2];
    const float* Wi = (const float*)d_in[3];
    const float* bi = (const float*)d_in[4];
    const float* Wh = (const float*)d_in[5];
    const float* bh = (const float*)d_in[6];
    float* out = (float*)d_out;

    cudaFuncSetAttribute(lstm_persist, cudaFuncAttributeMaxDynamicSharedMemorySize,
                         131072 + 16384);
    cudaFuncSetAttribute(xproj_mma_kernel, cudaFuncAttributeMaxDynamicSharedMemorySize,
                         XP_SMEM);

    init_kernel<<<(BB * HH + 255) / 256, 256>>>(h0, c0);
    conv_x_kernel<<<4096, 256>>>(x);
    conv_w_kernel<<<1024, 256>>>(Wi);

    float* xproj_ptr;
    cudaGetSymbolAddress((void**)&xproj_ptr, g_xproj);
    xproj_mma_kernel<<<dim3(32, 128), 256, XP_SMEM>>>(bi, bh, xproj_ptr);

    lstm_persist<<<128, 256, 131072 + 16384>>>(Wh, out);
    finish_kernel<<<(BB * HH + 255) / 256, 256>>>(out);
}

// round 10
// speedup vs baseline: 1.7828x; 1.3522x over previous
#include <cuda_runtime.h>
#include <cuda_bf16.h>
#include <math.h>
#include <stdint.h>

#define BB 32
#define TT 512
#define II 1024
#define HH 1024
#define GG 4096   // 4*H

// ---- scratch (static __device__ arrays; no allocation allowed) ----
__device__ float g_xproj[67108864];            // [T][B][4H] (256 MB)
__device__ float g_h[2][BB * HH];              // fp32 hidden (for h_T output)
__device__ __nv_bfloat16 g_hhi[2][BB * HH];    // bf16-split hidden ping-pong
__device__ __nv_bfloat16 g_hlo[2][BB * HH];
__device__ float g_c[BB * HH];
__device__ unsigned g_bar_cnt;
__device__ volatile unsigned g_bar_gen;
// bf16 hi/lo split operands for tensor-core xproj
__device__ __nv_bfloat16 g_xhi[TT * BB * II];  // [r=t*32+b][i]
__device__ __nv_bfloat16 g_xlo[TT * BB * II];
__device__ __nv_bfloat16 g_whi[GG * II];       // [n][k]
__device__ __nv_bfloat16 g_wlo[GG * II];

__device__ __forceinline__ float sigmoidf_(float x) {
    return 1.0f / (1.0f + __expf(-x));
}

__device__ __forceinline__ uint32_t smem_u32(const void* p) {
    uint32_t a;
    asm("{ .reg .u64 t; cvta.to.shared.u64 t, %1; cvt.u32.u64 %0, t; }"
        : "=r"(a) : "l"(p));
    return a;
}

// ldmatrix x4 (sm_75+)
__device__ __forceinline__ void ldsm4(uint32_t* r, uint32_t addr) {
    asm volatile("ldmatrix.sync.aligned.m8n8.x4.shared.b16 {%0,%1,%2,%3}, [%4];"
                 : "=r"(r[0]), "=r"(r[1]), "=r"(r[2]), "=r"(r[3]) : "r"(addr));
}
// mma.sync bf16 (sm_80+)
__device__ __forceinline__ void mma16816(float* c, const uint32_t* a,
                                         uint32_t b0, uint32_t b1) {
    asm volatile(
        "mma.sync.aligned.m16n8k16.row.col.f32.bf16.bf16.f32 "
        "{%0,%1,%2,%3}, {%4,%5,%6,%7}, {%8,%9}, {%0,%1,%2,%3};"
        : "+f"(c[0]), "+f"(c[1]), "+f"(c[2]), "+f"(c[3])
        : "r"(a[0]), "r"(a[1]), "r"(a[2]), "r"(a[3]), "r"(b0), "r"(b1));
}

// split a float into bf16 hi + bf16 lo
__device__ __forceinline__ void split1(float v, __nv_bfloat16& h, __nv_bfloat16& l) {
    h = __float2bfloat16(v);
    l = __float2bfloat16(v - __bfloat162float(h));
}

// ---------------------------------------------------------------------------
// init: h/c state, bf16-split h0, barrier reset
// ---------------------------------------------------------------------------
__global__ void init_kernel(const float* __restrict__ h0, const float* __restrict__ c0) {
    int i = blockIdx.x * blockDim.x + threadIdx.x;
    if (i < BB * HH) {
        float v = h0[i];
        g_h[0][i] = v;
        g_c[i] = c0[i];
        __nv_bfloat16 hi, lo;
        split1(v, hi, lo);
        g_hhi[0][i] = hi;
        g_hlo[0][i] = lo;
    }
    if (i == 0) { g_bar_cnt = 0; g_bar_gen = 0; }
}

__device__ __forceinline__ void split4(float4 v, __nv_bfloat16* hi, __nv_bfloat16* lo,
                                       size_t r) {
    float vv[4] = {v.x, v.y, v.z, v.w};
    __nv_bfloat16 h[4], l[4];
#pragma unroll
    for (int j = 0; j < 4; j++) split1(vv[j], h[j], l[j]);
    *(__nv_bfloat162*)(hi + r)     = __halves2bfloat162(h[0], h[1]);
    *(__nv_bfloat162*)(hi + r + 2) = __halves2bfloat162(h[2], h[3]);
    *(__nv_bfloat162*)(lo + r)     = __halves2bfloat162(l[0], l[1]);
    *(__nv_bfloat162*)(lo + r + 2) = __halves2bfloat162(l[2], l[3]);
}

__global__ void conv_x_kernel(const float* __restrict__ x) {
    int64_t n4 = (int64_t)TT * BB * II / 4;
    for (int64_t q = blockIdx.x * blockDim.x + threadIdx.x; q < n4;
         q += (int64_t)gridDim.x * blockDim.x) {
        int64_t i4 = q * 4;
        int i  = (int)(i4 & (II - 1));
        int bt = (int)(i4 >> 10);
        int t  = bt & (TT - 1);
        int b  = bt >> 9;
        float4 v = *(const float4*)(x + i4);
        size_t r = ((size_t)t * BB + b) * II + i;
        split4(v, g_xhi, g_xlo, r);
    }
}

__global__ void conv_w_kernel(const float* __restrict__ Wi) {
    int64_t n4 = (int64_t)GG * II / 4;
    for (int64_t q = blockIdx.x * blockDim.x + threadIdx.x; q < n4;
         q += (int64_t)gridDim.x * blockDim.x) {
        float4 v = *(const float4*)(Wi + q * 4);
        split4(v, g_whi, g_wlo, (size_t)q * 4);
    }
}

// ---------------------------------------------------------------------------
// xproj GEMM via mma.sync bf16 (validated R8 version, unchanged).
// ---------------------------------------------------------------------------
#define LDP 72
#define XP_SMEM (4 * 128 * LDP * 2)

__global__ __launch_bounds__(256, 2) void xproj_mma_kernel(
    const float* __restrict__ bi, const float* __restrict__ bh,
    float* __restrict__ outbuf)
{
    extern __shared__ char smem[];
    __nv_bfloat16* Ah = (__nv_bfloat16*)smem;
    __nv_bfloat16* Al = Ah + 128 * LDP;
    __nv_bfloat16* Bh = Al + 128 * LDP;
    __nv_bfloat16* Bl = Bh + 128 * LDP;

    const int tid  = threadIdx.x;
    const int w    = tid >> 5;
    const int lane = tid & 31;
    const int ntile = blockIdx.x;
    const int mtile = blockIdx.y;
    const int wm = (w >> 1) * 32;
    const int wn = (w & 1) * 64;

    const __nv_bfloat16* gAh = g_xhi + (size_t)(mtile * 128) * II;
    const __nv_bfloat16* gAl = g_xlo + (size_t)(mtile * 128) * II;
    const __nv_bfloat16* gBh = g_whi + (size_t)(ntile * 128) * II;
    const __nv_bfloat16* gBl = g_wlo + (size_t)(ntile * 128) * II;

    float acc[2][8][4];
#pragma unroll
    for (int mi = 0; mi < 2; mi++)
#pragma unroll
        for (int nj = 0; nj < 8; nj++)
#pragma unroll
            for (int q = 0; q < 4; q++) acc[mi][nj][q] = 0.f;

    const int a_row = lane & 15;
    const int a_col = (lane >> 4) << 3;
    const int b_row = ((lane >> 4) << 3) + (lane & 7);
    const int b_col = ((lane >> 3) & 1) << 3;

    for (int chunk = 0; chunk < 16; chunk++) {
        const int k0 = chunk * 64;
#pragma unroll
        for (int it = 0; it < 4; it++) {
            int idx = tid + it * 256;
            int row = idx >> 3;
            int cg  = idx & 7;
            size_t g = (size_t)row * II + k0 + cg * 8;
            int s = row * LDP + cg * 8;
            *(uint4*)(Ah + s) = *(const uint4*)(gAh + g);
            *(uint4*)(Al + s) = *(const uint4*)(gAl + g);
            *(uint4*)(Bh + s) = *(const uint4*)(gBh + g);
            *(uint4*)(Bl + s) = *(const uint4*)(gBl + g);
        }
        __syncthreads();

#pragma unroll
        for (int kk = 0; kk < 4; kk++) {
            const int ks = kk * 16;
            uint32_t ah[2][4], al[2][4];
#pragma unroll
            for (int mi = 0; mi < 2; mi++) {
                ldsm4(ah[mi], smem_u32(Ah + (wm + mi * 16 + a_row) * LDP + ks + a_col));
                ldsm4(al[mi], smem_u32(Al + (wm + mi * 16 + a_row) * LDP + ks + a_col));
            }
#pragma unroll
            for (int g2 = 0; g2 < 4; g2++) {
                uint32_t bh4[4], bl4[4];
                ldsm4(bh4, smem_u32(Bh + (wn + g2 * 16 + b_row) * LDP + ks + b_col));
                ldsm4(bl4, smem_u32(Bl + (wn + g2 * 16 + b_row) * LDP + ks + b_col));
#pragma unroll
                for (int mi = 0; mi < 2; mi++) {
                    mma16816(acc[mi][g2 * 2],     ah[mi], bh4[0], bh4[1]);
                    mma16816(acc[mi][g2 * 2],     ah[mi], bl4[0], bl4[1]);
                    mma16816(acc[mi][g2 * 2],     al[mi], bh4[0], bh4[1]);
                    mma16816(acc[mi][g2 * 2 + 1], ah[mi], bh4[2], bh4[3]);
                    mma16816(acc[mi][g2 * 2 + 1], ah[mi], bl4[2], bl4[3]);
                    mma16816(acc[mi][g2 * 2 + 1], al[mi], bh4[2], bh4[3]);
                }
            }
        }
        __syncthreads();
    }

    const int colw = ntile * 128 + wn;
#pragma unroll
    for (int mi = 0; mi < 2; mi++) {
        int r0 = mtile * 128 + wm + mi * 16 + (lane >> 2);
#pragma unroll
        for (int nj = 0; nj < 8; nj++) {
            int c = colw + nj * 8 + (lane & 3) * 2;
            float b0 = bi[c] + bh[c];
            float b1 = bi[c + 1] + bh[c + 1];
            *(float2*)(outbuf + (size_t)r0 * GG + c) =
                make_float2(acc[mi][nj][0] + b0, acc[mi][nj][1] + b1);
            *(float2*)(outbuf + (size_t)(r0 + 8) * GG + c) =
                make_float2(acc[mi][nj][2] + b0, acc[mi][nj][3] + b1);
        }
    }
}

// ---------------------------------------------------------------------------
// Persistent tensor-core recurrence.
// 128 blocks x 256 thr (8 warps), 1 CTA/SM. Block bx owns 8 h-columns
// [bx*8, bx*8+8) = 32 gate cols (4 gates x 8), FULL K=1024 -> no partials.
// Wh slice (hi+lo bf16, 32 x 1024, padded) resident in SMEM all steps.
// Warp w = mt*4 + kq: mt = m-tile (16 rows), kq = K quarter (256).
// Fixed-order cross-warp reduction in SMEM -> deterministic.
// One grid barrier per step.
// ---------------------------------------------------------------------------
#define LDKW 1032                        // padded row stride (bf16): 2064 B
#define RC_WH   (32 * LDKW * 2)          // one Wh buffer bytes (66048)
#define RC_RED  (6 * 32 * 16 * 4)       // 12288 B
#define RC_GATE (32 * 33 * 4)           // 4224 B
#define RC_SMEM (2 * RC_WH + RC_RED + RC_GATE)

__device__ __forceinline__ void grid_sync(unsigned& gen) {
    __syncthreads();
    if (threadIdx.x == 0) {
        __threadfence();
        unsigned arrived = atomicAdd(&g_bar_cnt, 1u);
        if (arrived == gridDim.x - 1) {
            g_bar_cnt = 0;
            __threadfence();
            g_bar_gen = gen + 1;
        } else {
            while (g_bar_gen <= gen) { }
            __threadfence();
        }
    }
    gen++;
    __syncthreads();
}

__global__ __launch_bounds__(256, 1) void lstm_persist_tc(
    const float* __restrict__ Wh, float* __restrict__ out)
{
    extern __shared__ char smem_raw[];
    __nv_bfloat16* WhHi = (__nv_bfloat16*)smem_raw;                 // [32][LDKW]
    __nv_bfloat16* WhLo = WhHi + 32 * LDKW;
    float* red   = (float*)(smem_raw + 2 * RC_WH);                  // [6][32][16]
    float* gates = (float*)(smem_raw + 2 * RC_WH + RC_RED);         // [32][33]

    const int bx    = blockIdx.x;
    const int tid   = threadIdx.x;
    const int w     = tid >> 5;
    const int lane  = tid & 31;
    const int mt    = w >> 2;        // 0..1 (m-tile of 16)
    const int kq    = w & 3;         // 0..3 (K quarter)
    const int hbase = bx * 8;

    // ---- one-time: load + split Wh slice into SMEM ----
    // smem row n = gate*8 + hcl  <->  global row gate*1024 + hbase + hcl
    {
        const int n  = tid >> 3;         // 0..31
        const int cq = tid & 7;          // k chunk of 128
        const int grow = (n >> 3) * HH + hbase + (n & 7);
        const float* src = Wh + (size_t)grow * HH;
#pragma unroll 4
        for (int kk = 0; kk < 16; kk++) {
            int k = cq * 128 + kk * 8;
            float4 va = *(const float4*)(src + k);
            float4 vb = *(const float4*)(src + k + 4);
            float vv[8] = {va.x, va.y, va.z, va.w, vb.x, vb.y, vb.z, vb.w};
            __nv_bfloat16 h[8], l[8];
#pragma unroll
            for (int j = 0; j < 8; j++) split1(vv[j], h[j], l[j]);
            __nv_bfloat162* dh = (__nv_bfloat162*)(WhHi + n * LDKW + k);
            __nv_bfloat162* dl = (__nv_bfloat162*)(WhLo + n * LDKW + k);
#pragma unroll
            for (int j = 0; j < 4; j++) {
                dh[j] = __halves2bfloat162(h[2 * j], h[2 * j + 1]);
                dl[j] = __halves2bfloat162(l[2 * j], l[2 * j + 1]);
            }
        }
    }
    __syncthreads();

    const int b_row = ((lane >> 4) << 3) + (lane & 7);
    const int b_col = ((lane >> 3) & 1) << 3;
    const uint32_t bhi0_base = smem_u32(WhHi + b_row * LDKW + b_col);
    const uint32_t bhi1_base = smem_u32(WhHi + (16 + b_row) * LDKW + b_col);
    const uint32_t blo0_base = smem_u32(WhLo + b_row * LDKW + b_col);
    const uint32_t blo1_base = smem_u32(WhLo + (16 + b_row) * LDKW + b_col);

    // A-frag global index components (m16n8k16 lane map)
    const int ar0 = mt * 16 + (lane >> 2);       // batch rows ar0 and ar0+8
    const int ak  = (lane & 3) * 2;

    const int rb  = tid >> 3;   // activation role: batch
    const int rhc = tid & 7;    // activation role: local h col

    unsigned gen = 0;

    for (int t = 0; t < TT; t++) {
        const uint32_t* hhi = (const uint32_t*)g_hhi[t & 1];
        const uint32_t* hlo = (const uint32_t*)g_hlo[t & 1];

        float acc[4][4];
#pragma unroll
        for (int f = 0; f < 4; f++)
#pragma unroll
            for (int q = 0; q < 4; q++) acc[f][q] = 0.f;

        // ---- K loop: this warp's quarter ----
#pragma unroll 2
        for (int it = 0; it < 16; it++) {
            const int k = kq * 256 + it * 16;
            uint32_t ah[4], al[4];
            const int i00 = (ar0 * HH + k + ak) >> 1;
            const int i10 = ((ar0 + 8) * HH + k + ak) >> 1;
            ah[0] = hhi[i00];     ah[1] = hhi[i10];
            ah[2] = hhi[i00 + 4]; ah[3] = hhi[i10 + 4];
            al[0] = hlo[i00];     al[1] = hlo[i10];
            al[2] = hlo[i00 + 4]; al[3] = hlo[i10 + 4];

            uint32_t bh0[4], bh1[4], bl0[4], bl1[4];
            ldsm4(bh0, bhi0_base + k * 2);
            ldsm4(bh1, bhi1_base + k * 2);
            ldsm4(bl0, blo0_base + k * 2);
            ldsm4(bl1, blo1_base + k * 2);

            mma16816(acc[0], ah, bh0[0], bh0[1]);
            mma16816(acc[1], ah, bh0[2], bh0[3]);
            mma16816(acc[2], ah, bh1[0], bh1[1]);
            mma16816(acc[3], ah, bh1[2], bh1[3]);
            mma16816(acc[0], ah, bl0[0], bl0[1]);
            mma16816(acc[1], ah, bl0[2], bl0[3]);
            mma16816(acc[2], ah, bl1[0], bl1[1]);
            mma16816(acc[3], ah, bl1[2], bl1[3]);
            mma16816(acc[0], al, bh0[0], bh0[1]);
            mma16816(acc[1], al, bh0[2], bh0[3]);
            mma16816(acc[2], al, bh1[0], bh1[1]);
            mma16816(acc[3], al, bh1[2], bh1[3]);
        }

        // ---- cross-warp K reduction (fixed order -> deterministic) ----
        if (kq != 0) {
            float* rdst = red + ((mt * 3 + (kq - 1)) * 32 + lane) * 16;
#pragma unroll
            for (int f = 0; f < 4; f++)
#pragma unroll
                for (int q = 0; q < 4; q++) rdst[f * 4 + q] = acc[f][q];
        }
        __syncthreads();
        if (kq == 0) {
#pragma unroll
            for (int p = 0; p < 3; p++) {
                const float* rsrc = red + ((mt * 3 + p) * 32 + lane) * 16;
#pragma unroll
                for (int f = 0; f < 4; f++)
#pragma unroll
                    for (int q = 0; q < 4; q++) acc[f][q] += rsrc[f * 4 + q];
            }
            // write gates tile: rows mt*16 + r(+8), cols f*8 + (lane&3)*2 (+1)
            const int r0 = mt * 16 + (lane >> 2);
            const int c0 = (lane & 3) * 2;
#pragma unroll
            for (int f = 0; f < 4; f++) {
                gates[r0 * 33 + f * 8 + c0]           = acc[f][0];
                gates[r0 * 33 + f * 8 + c0 + 1]       = acc[f][1];
                gates[(r0 + 8) * 33 + f * 8 + c0]     = acc[f][2];
                gates[(r0 + 8) * 33 + f * 8 + c0 + 1] = acc[f][3];
            }
        }
        __syncthreads();

        // ---- activations: thread = (batch rb, local col rhc) ----
        {
            const float* xp = g_xproj + ((size_t)t * BB + rb) * GG + hbase + rhc;
            float s_i = gates[rb * 33 + rhc]      + xp[0];
            float s_f = gates[rb * 33 + 8 + rhc]  + xp[HH];
            float s_g = gates[rb * 33 + 16 + rhc] + xp[2 * HH];
            float s_o = gates[rb * 33 + 24 + rhc] + xp[3 * HH];

            float ig = sigmoidf_(s_i);
            float fg = sigmoidf_(s_f);
            float gg = tanhf(s_g);
            float og = sigmoidf_(s_o);

            const int hc  = hbase + rhc;
            const int idx = rb * HH + hc;
            float c_old = g_c[idx];
            float c_new = fmaf(fg, c_old, ig * gg);
            float h_new = og * tanhf(c_new);
            g_c[idx] = c_new;
            g_h[(t + 1) & 1][idx] = h_new;
            __nv_bfloat16 hi, lo;
            split1(h_new, hi, lo);
            g_hhi[(t + 1) & 1][idx] = hi;
            g_hlo[(t + 1) & 1][idx] = lo;
            out[(size_t)rb * TT * HH + (size_t)t * HH + hc] = h_new;
        }

        grid_sync(gen);   // h fully published before next step reads it
    }
}

// ---------------------------------------------------------------------------
// tail: h_T, c_T appended after output [B,T,H]
// ---------------------------------------------------------------------------
__global__ void finish_kernel(float* __restrict__ out) {
    int i = blockIdx.x * blockDim.x + threadIdx.x;
    if (i < BB * HH) {
        out[(size_t)BB * TT * HH + i]           = g_h[0][i];   // 512 steps -> buf 0
        out[(size_t)BB * TT * HH + BB * HH + i] = g_c[i];
    }
}

extern "C" void kernel_launch(void* const* d_in, const int* in_sizes, int n_in,
                              void* d_out, int out_size) {
    const float* x  = (const float*)d_in[0];
    const float* h0 = (const float*)d_in[1];
    const float* c0 = (const float*)d_in[2];
    const float* Wi = (const float*)d_in[3];
    const float* bi = (const float*)d_in[4];
    const float* Wh = (const float*)d_in[5];
    const float* bh = (const float*)d_in[6];
    float* out = (float*)d_out;

    cudaFuncSetAttribute(xproj_mma_kernel, cudaFuncAttributeMaxDynamicSharedMemorySize,
                         XP_SMEM);
    cudaFuncSetAttribute(lstm_persist_tc, cudaFuncAttributeMaxDynamicSharedMemorySize,
                         RC_SMEM);

    init_kernel<<<(BB * HH + 255) / 256, 256>>>(h0, c0);
    conv_x_kernel<<<4096, 256>>>(x);
    conv_w_kernel<<<1024, 256>>>(Wi);

    float* xproj_ptr;
    cudaGetSymbolAddress((void**)&xproj_ptr, g_xproj);
    xproj_mma_kernel<<<dim3(32, 128), 256, XP_SMEM>>>(bi, bh, xproj_ptr);

    lstm_persist_tc<<<128, 256, RC_SMEM>>>(Wh, out);
    finish_kernel<<<(BB * HH + 255) / 256, 256>>>(out);
}